// round 13
// baseline (speedup 1.0000x reference)
#include <cuda_runtime.h>
#include <cuda_bf16.h>
#include <cstdint>

// Problem constants
#define B_  2
#define S_  1024
#define H_  2048
#define NH_ 32
#define NKV_ 8
#define HD_ 64
#define M_  2048

// ---------------------------------------------------------------------------
// Scratch (device globals)
// ---------------------------------------------------------------------------
__device__ float g_qraw[M_ * 2048];
__device__ float g_kraw[M_ * 512];
__device__ float g_vraw[M_ * 512];
__device__ float g_ctx[M_ * 2048];
// flash packed bf16x2 operands
__device__ uint32_t g_QH[M_ * 1024], g_QL[M_ * 1024];
__device__ uint32_t g_KHp[524288],   g_KLp[524288];
__device__ uint32_t g_VHp[524288],   g_VLp[524288];
// int8 GEMM operands
__device__ uint32_t g_A1[512 * 2048], g_A2[512 * 2048];
__device__ uint32_t g_WQ1[512 * 2048], g_WQ2[512 * 2048];
__device__ uint32_t g_WK1[512 * 512],  g_WK2[512 * 512];
__device__ uint32_t g_WV1[512 * 512],  g_WV2[512 * 512];
__device__ uint32_t g_WO1[512 * 2048], g_WO2[512 * 2048];
// abs-max arrays
__device__ float g_mxA[2048];
__device__ float g_mxC[2048];
__device__ float g_mxQ[2048], g_mxK[512], g_mxV[512], g_mxO[2048];

// ---------------------------------------------------------------------------
// helpers
// ---------------------------------------------------------------------------
__device__ __forceinline__ void mma_bf16(
    float& c0, float& c1, float& c2, float& c3,
    uint32_t a0, uint32_t a1, uint32_t a2, uint32_t a3,
    uint32_t b0, uint32_t b1)
{
    asm volatile(
        "mma.sync.aligned.m16n8k16.row.col.f32.bf16.bf16.f32 "
        "{%0,%1,%2,%3}, {%4,%5,%6,%7}, {%8,%9}, {%0,%1,%2,%3};\n"
        : "+f"(c0), "+f"(c1), "+f"(c2), "+f"(c3)
        : "r"(a0), "r"(a1), "r"(a2), "r"(a3), "r"(b0), "r"(b1));
}

__device__ __forceinline__ void mma_s8(
    int& c0, int& c1, int& c2, int& c3,
    uint32_t a0, uint32_t a1, uint32_t a2, uint32_t a3,
    uint32_t b0, uint32_t b1)
{
    asm volatile(
        "mma.sync.aligned.m16n8k32.row.col.s32.s8.s8.s32 "
        "{%0,%1,%2,%3}, {%4,%5,%6,%7}, {%8,%9}, {%0,%1,%2,%3};\n"
        : "+r"(c0), "+r"(c1), "+r"(c2), "+r"(c3)
        : "r"(a0), "r"(a1), "r"(a2), "r"(a3), "r"(b0), "r"(b1));
}

__device__ __forceinline__ void cp16(uint32_t dst, const void* src) {
    asm volatile("cp.async.cg.shared.global [%0], [%1], 16;" :: "r"(dst), "l"(src));
}

__device__ __forceinline__ uint32_t pack_hi(float x, float y) {
    __nv_bfloat162 h = __floats2bfloat162_rn(x, y);
    return *reinterpret_cast<uint32_t*>(&h);
}
__device__ __forceinline__ uint32_t pack_lo(float x, float y, uint32_t hi) {
    __nv_bfloat162 h = *reinterpret_cast<__nv_bfloat162*>(&hi);
    float lx = x - __bfloat162float(h.x);
    float ly = y - __bfloat162float(h.y);
    __nv_bfloat162 l = __floats2bfloat162_rn(lx, ly);
    return *reinterpret_cast<uint32_t*>(&l);
}

__device__ __forceinline__ float quant_r127(float mx) {
    int e; frexpf(mx, &e);
    return 127.f * exp2f((float)(-e));
}
__device__ __forceinline__ float scl(float mx) {
    int e; frexpf(mx, &e);
    return exp2f((float)e) * (1.f / 127.f);
}
__device__ __forceinline__ void quant2(float x, float r127, int& q1, int& q2) {
    float a1 = rintf(x * r127);
    float r = fmaf(x, r127, -a1);
    float a2 = rintf(r * 256.f);
    a2 = fminf(fmaxf(a2, -127.f), 127.f);
    q1 = (int)a1; q2 = (int)a2;
}
__device__ __forceinline__ uint32_t pack4(int a, int b, int c, int d) {
    return (uint32_t)(a & 0xff) | ((uint32_t)(b & 0xff) << 8) |
           ((uint32_t)(c & 0xff) << 16) | ((uint32_t)(d & 0xff) << 24);
}

// ---------------------------------------------------------------------------
// reductions
// ---------------------------------------------------------------------------
__device__ __forceinline__ float block_sum_256(float v) {
    __shared__ float red[8];
#pragma unroll
    for (int o = 16; o > 0; o >>= 1) v += __shfl_xor_sync(0xffffffffu, v, o);
    const int lane = threadIdx.x & 31, wid = threadIdx.x >> 5;
    if (lane == 0) red[wid] = v;
    __syncthreads();
    float tot = 0.f;
    if (threadIdx.x < 8) tot = red[threadIdx.x];
#pragma unroll
    for (int o = 4; o > 0; o >>= 1) tot += __shfl_xor_sync(0xffffffffu, tot, o);
    return tot;
}

__device__ __forceinline__ float block_max_256(float v) {
    __shared__ float red[8];
#pragma unroll
    for (int o = 16; o > 0; o >>= 1) v = fmaxf(v, __shfl_xor_sync(0xffffffffu, v, o));
    const int lane = threadIdx.x & 31, wid = threadIdx.x >> 5;
    if (lane == 0) red[wid] = v;
    __syncthreads();
    float tot = 0.f;
    if (threadIdx.x < 8) tot = red[threadIdx.x];
#pragma unroll
    for (int o = 4; o > 0; o >>= 1) tot = fmaxf(tot, __shfl_xor_sync(0xffffffffu, tot, o));
    return tot;
}

// ---------------------------------------------------------------------------
// fused scale prep (R12, proven)
// ---------------------------------------------------------------------------
__global__ __launch_bounds__(256) void zero_all(
    float* a, float* b, float* c, float* d, float* e)
{
    const int i = blockIdx.x * 256 + threadIdx.x;
    if (i < 2048) { a[i] = 0.f; d[i] = 0.f; e[i] = 0.f; }
    if (i < 512)  { b[i] = 0.f; c[i] = 0.f; }
}

__global__ __launch_bounds__(256) void colmax_all(
    const float* __restrict__ wq, const float* __restrict__ wk,
    const float* __restrict__ wv, const float* __restrict__ wo,
    float* __restrict__ mxQ, float* __restrict__ mxK,
    float* __restrict__ mxV, float* __restrict__ mxO)
{
    __shared__ float s[4][64];
    int bx = blockIdx.x;
    const float* W; float* mx; int N;
    if (bx < 32)      { W = wq; mx = mxQ; N = 2048; }
    else if (bx < 40) { W = wk; mx = mxK; N = 512; bx -= 32; }
    else if (bx < 48) { W = wv; mx = mxV; N = 512; bx -= 40; }
    else              { W = wo; mx = mxO; N = 2048; bx -= 48; }
    const int n0 = bx * 64, k0 = blockIdx.y * 256;
    const int c = threadIdx.x & 63, r = threadIdx.x >> 6;
    float v = 0.f;
#pragma unroll 8
    for (int j = 0; j < 64; j++)
        v = fmaxf(v, fabsf(W[(size_t)(k0 + 4 * j + r) * N + n0 + c]));
    s[r][c] = v;
    __syncthreads();
    if (r == 0) {
        float m = fmaxf(fmaxf(s[0][c], s[1][c]), fmaxf(s[2][c], s[3][c]));
        atomicMax((unsigned int*)&mx[n0 + c], __float_as_uint(m));
    }
}

__global__ __launch_bounds__(256) void quant_w_all(
    const float* __restrict__ wq, const float* __restrict__ wk,
    const float* __restrict__ wv, const float* __restrict__ wo,
    const float* __restrict__ mxQ, const float* __restrict__ mxK,
    const float* __restrict__ mxV, const float* __restrict__ mxO,
    uint32_t* __restrict__ WQ1, uint32_t* __restrict__ WQ2,
    uint32_t* __restrict__ WK1, uint32_t* __restrict__ WK2,
    uint32_t* __restrict__ WV1, uint32_t* __restrict__ WV2,
    uint32_t* __restrict__ WO1, uint32_t* __restrict__ WO2)
{
    int i = blockIdx.x * 256 + threadIdx.x;
    const float* W; const float* mx; uint32_t *B1, *B2; int N;
    if (i < 1048576)      { W = wq; mx = mxQ; B1 = WQ1; B2 = WQ2; N = 2048; }
    else if (i < 1310720) { W = wk; mx = mxK; B1 = WK1; B2 = WK2; N = 512; i -= 1048576; }
    else if (i < 1572864) { W = wv; mx = mxV; B1 = WV1; B2 = WV2; N = 512; i -= 1310720; }
    else                  { W = wo; mx = mxO; B1 = WO1; B2 = WO2; N = 2048; i -= 1572864; }
    const int kq = i / N, n = i - kq * N;
    const float r127 = quant_r127(mx[n]);
    int q1[4], q2[4];
#pragma unroll
    for (int j = 0; j < 4; j++)
        quant2(W[(size_t)(4 * kq + j) * N + n], r127, q1[j], q2[j]);
    B1[i] = pack4(q1[0], q1[1], q1[2], q1[3]);
    B2[i] = pack4(q2[0], q2[1], q2[2], q2[3]);
}

__global__ __launch_bounds__(256) void rowmax(
    const float* __restrict__ X, float* __restrict__ mx, int K)
{
    const int r = blockIdx.x;
    const float4* row = reinterpret_cast<const float4*>(X + (size_t)r * K);
    const int n4 = K >> 2;
    float v = 0.f;
    for (int k = threadIdx.x; k < n4; k += 256) {
        float4 x = row[k];
        v = fmaxf(v, fmaxf(fmaxf(fabsf(x.x), fabsf(x.y)),
                           fmaxf(fabsf(x.z), fabsf(x.w))));
    }
    float tot = block_max_256(v);
    if (threadIdx.x == 0) mx[r] = tot;
}

__global__ __launch_bounds__(256) void tquant(
    const float* __restrict__ X, const float* __restrict__ mxRow,
    uint32_t* __restrict__ A1, uint32_t* __restrict__ A2, int M, int K)
{
    __shared__ float t[64][33];
    const int m0 = blockIdx.x * 32, k0 = blockIdx.y * 64;
#pragma unroll
    for (int i = threadIdx.x; i < 32 * 64; i += 256) {
        const int ml = i >> 6, kl = i & 63;
        t[kl][ml] = X[(size_t)(m0 + ml) * K + k0 + kl];
    }
    __syncthreads();
#pragma unroll
    for (int i = threadIdx.x; i < 32 * 16; i += 256) {
        const int kql = i >> 5, ml = i & 31;
        const float r127 = quant_r127(mxRow[m0 + ml]);
        int q1[4], q2[4];
#pragma unroll
        for (int j = 0; j < 4; j++)
            quant2(t[4 * kql + j][ml], r127, q1[j], q2[j]);
        const size_t o = (size_t)(k0 / 4 + kql) * M + m0 + ml;
        A1[o] = pack4(q1[0], q1[1], q1[2], q1[3]);
        A2[o] = pack4(q2[0], q2[1], q2[2], q2[3]);
    }
}

// ---------------------------------------------------------------------------
// int8 split GEMM body (R9, proven)
// ---------------------------------------------------------------------------
#define KPT 8
#define PITCH 132
#define PLANE_W (KPT * PITCH)
#define STG_W (4 * PLANE_W)
#define STG_BYTES (STG_W * 4)
#define G2_SMEM (4 * STG_BYTES)

__device__ __forceinline__ void gemm_i8_body(
    const uint32_t* __restrict__ A1g, const uint32_t* __restrict__ A2g,
    const uint32_t* __restrict__ B1g, const uint32_t* __restrict__ B2g,
    const float* __restrict__ mxRow, const float* __restrict__ mxCol,
    float* __restrict__ C, int AM, int N, int K, int brow, int bcol)
{
    extern __shared__ uint32_t sm2[];

    const int tid  = threadIdx.x;
    const int lane = tid & 31;
    const int warp = tid >> 5;
    const int gid  = lane >> 2;
    const int tig  = lane & 3;
    const int wm   = (warp & 3) * 32;
    const int wn   = (warp >> 2) * 64;

    uint32_t sbase;
    asm("{ .reg .u64 t; cvta.to.shared.u64 t, %1; cvt.u32.u64 %0, t; }"
        : "=r"(sbase) : "l"(sm2));

    const int NK = K >> 5;
    const int l_row = tid >> 5;
    const int l_ch  = tid & 31;

    auto load_stage = [&](int kt) {
        const uint32_t st = sbase + (kt & 3) * STG_BYTES;
        const size_t kqg = (size_t)(kt * KPT + l_row);
        const size_t aoff = kqg * AM + brow + l_ch * 4;
        const size_t boff = kqg * N + bcol + l_ch * 4;
        const uint32_t d0 = st + l_row * (PITCH * 4) + l_ch * 16;
        cp16(d0,                       A1g + aoff);
        cp16(d0 + PLANE_W * 4,         A2g + aoff);
        cp16(d0 + 2 * (PLANE_W * 4),   B1g + boff);
        cp16(d0 + 3 * (PLANE_W * 4),   B2g + boff);
    };

    int c1[2][8][4], c2[2][8][4];
#pragma unroll
    for (int i = 0; i < 2; i++)
#pragma unroll
        for (int j = 0; j < 8; j++)
#pragma unroll
            for (int v = 0; v < 4; v++) { c1[i][j][v] = 0; c2[i][j][v] = 0; }

    load_stage(0);
    asm volatile("cp.async.commit_group;" ::: "memory");
    load_stage(1);
    asm volatile("cp.async.commit_group;" ::: "memory");
    load_stage(2);
    asm volatile("cp.async.commit_group;" ::: "memory");

    for (int kt = 0; kt < NK; kt++) {
        asm volatile("cp.async.wait_group 2;" ::: "memory");
        __syncthreads();

        const uint32_t* A1s = sm2 + (kt & 3) * STG_W;
        const uint32_t* A2s = A1s + PLANE_W;
        const uint32_t* B1s = A1s + 2 * PLANE_W;
        const uint32_t* B2s = A1s + 3 * PLANE_W;

        uint32_t a1f[2][4], a2f[2][4];
#pragma unroll
        for (int mt = 0; mt < 2; mt++) {
            const int m0 = wm + mt * 16 + gid;
            a1f[mt][0] = A1s[tig * PITCH + m0];
            a1f[mt][1] = A1s[tig * PITCH + m0 + 8];
            a1f[mt][2] = A1s[(tig + 4) * PITCH + m0];
            a1f[mt][3] = A1s[(tig + 4) * PITCH + m0 + 8];
            a2f[mt][0] = A2s[tig * PITCH + m0];
            a2f[mt][1] = A2s[tig * PITCH + m0 + 8];
            a2f[mt][2] = A2s[(tig + 4) * PITCH + m0];
            a2f[mt][3] = A2s[(tig + 4) * PITCH + m0 + 8];
        }
#pragma unroll
        for (int nt = 0; nt < 8; nt++) {
            const int n0 = wn + nt * 8 + gid;
            const uint32_t b10 = B1s[tig * PITCH + n0];
            const uint32_t b11 = B1s[(tig + 4) * PITCH + n0];
            const uint32_t b20 = B2s[tig * PITCH + n0];
            const uint32_t b21 = B2s[(tig + 4) * PITCH + n0];
#pragma unroll
            for (int mt = 0; mt < 2; mt++) {
                int* p1 = c1[mt][nt];
                int* p2 = c2[mt][nt];
                mma_s8(p1[0], p1[1], p1[2], p1[3],
                       a1f[mt][0], a1f[mt][1], a1f[mt][2], a1f[mt][3], b10, b11);
                mma_s8(p2[0], p2[1], p2[2], p2[3],
                       a1f[mt][0], a1f[mt][1], a1f[mt][2], a1f[mt][3], b20, b21);
                mma_s8(p2[0], p2[1], p2[2], p2[3],
                       a2f[mt][0], a2f[mt][1], a2f[mt][2], a2f[mt][3], b10, b11);
            }
        }

        __syncthreads();
        if (kt + 3 < NK) load_stage(kt + 3);
        asm volatile("cp.async.commit_group;" ::: "memory");
    }

#pragma unroll
    for (int mt = 0; mt < 2; mt++) {
        const int r0 = brow + wm + mt * 16 + gid;
        const float sr0 = scl(mxRow[r0]);
        const float sr1 = scl(mxRow[r0 + 8]);
#pragma unroll
        for (int nt = 0; nt < 8; nt++) {
            const int col = bcol + wn + nt * 8 + 2 * tig;
            const float sc0 = scl(mxCol[col]);
            const float sc1 = scl(mxCol[col + 1]);
            const int* p1 = c1[mt][nt];
            const int* p2 = c2[mt][nt];
            const float v0 = (float)p1[0] + (float)p2[0] * (1.f / 256.f);
            const float v1 = (float)p1[1] + (float)p2[1] * (1.f / 256.f);
            const float v2 = (float)p1[2] + (float)p2[2] * (1.f / 256.f);
            const float v3 = (float)p1[3] + (float)p2[3] * (1.f / 256.f);
            *reinterpret_cast<float2*>(C + (size_t)r0 * N + col) =
                make_float2(sr0 * sc0 * v0, sr0 * sc1 * v1);
            *reinterpret_cast<float2*>(C + (size_t)(r0 + 8) * N + col) =
                make_float2(sr1 * sc0 * v2, sr1 * sc1 * v3);
        }
    }
}

__global__ __launch_bounds__(256) void gemm_i8_qkv(
    const uint32_t* __restrict__ A1g, const uint32_t* __restrict__ A2g,
    const uint32_t* __restrict__ Q1g, const uint32_t* __restrict__ Q2g,
    const uint32_t* __restrict__ K1g, const uint32_t* __restrict__ K2g,
    const uint32_t* __restrict__ V1g, const uint32_t* __restrict__ V2g,
    const float* __restrict__ mxRow,
    const float* __restrict__ mxQ, const float* __restrict__ mxK,
    const float* __restrict__ mxV,
    float* __restrict__ Cq, float* __restrict__ Ck, float* __restrict__ Cv)
{
    const int x = blockIdx.x;
    if (x < 16) {
        gemm_i8_body(A1g, A2g, Q1g, Q2g, mxRow, mxQ, Cq, 2048, 2048, 2048,
                     blockIdx.y * 128, x * 128);
    } else {
        const int xx = x - 16;
        const bool isv = xx >= 4;
        const int bx = xx & 3;
        gemm_i8_body(A1g, A2g, isv ? V1g : K1g, isv ? V2g : K2g,
                     mxRow, isv ? mxV : mxK, isv ? Cv : Ck,
                     2048, 512, 2048, blockIdx.y * 128, bx * 128);
    }
}

__global__ __launch_bounds__(256) void gemm_i8(
    const uint32_t* __restrict__ A1g, const uint32_t* __restrict__ A2g,
    const uint32_t* __restrict__ B1g, const uint32_t* __restrict__ B2g,
    const float* __restrict__ mxRow, const float* __restrict__ mxCol,
    float* __restrict__ C, int AM, int N, int K)
{
    gemm_i8_body(A1g, A2g, B1g, B2g, mxRow, mxCol, C, AM, N, K,
                 blockIdx.y * 128, blockIdx.x * 128);
}

// ---------------------------------------------------------------------------
// Fused norm/rope/pack (R10, proven): grid 6144
// ---------------------------------------------------------------------------
__global__ __launch_bounds__(256) void normpack_all(
    const float* __restrict__ qraw, const float* __restrict__ kraw,
    const float* __restrict__ vraw,
    const float* __restrict__ qw, const float* __restrict__ kw,
    const float* __restrict__ cosb, const float* __restrict__ sinb,
    uint32_t* __restrict__ QH, uint32_t* __restrict__ QL,
    uint32_t* __restrict__ KH, uint32_t* __restrict__ KL,
    uint32_t* __restrict__ VH, uint32_t* __restrict__ VL)
{
    const int blk = blockIdx.x;
    if (blk < 2048) {
        const int r = blk;
        const int b = r >> 10, s = r & 1023;
        const float* row = qraw + (size_t)r * 2048;

        float ss = 0.f;
        for (int d = threadIdx.x; d < 2048; d += 256) { float x = row[d]; ss += x * x; }
        float tot = block_sum_256(ss);
        __shared__ float s_inv_q;
        if (threadIdx.x == 0) s_inv_q = rsqrtf(tot * (1.f / 2048.f) + 1e-6f);
        __syncthreads();
        const float inv = s_inv_q;

        const float* cs = cosb + (size_t)r * 64;
        const float* sn = sinb + (size_t)r * 64;

        for (int p = threadIdx.x; p < 1024; p += 256) {
            const int h = p >> 5, hdp = p & 31;
            float o2[2];
#pragma unroll
            for (int j = 0; j < 2; j++) {
                const int hd = 2 * hdp + j, d = h * 64 + hd;
                float val = row[d] * inv * qw[d];
                const int pd = (hd < 32) ? d + 32 : d - 32;
                float pv = row[pd] * inv * qw[pd];
                float rot = (hd < 32) ? -pv : pv;
                o2[j] = val * cs[hd] + rot * sn[hd];
            }
            const uint32_t hb = pack_hi(o2[0], o2[1]);
            const size_t oi = (((size_t)(b * NH_ + h)) * S_ + s) * 32 + hdp;
            QH[oi] = hb;
            QL[oi] = pack_lo(o2[0], o2[1], hb);
        }
    } else if (blk < 4096) {
        const int r = blk - 2048;
        const int b = r >> 10, s = r & 1023;
        const float* row = kraw + (size_t)r * 512;

        float ss = 0.f;
        for (int d = threadIdx.x; d < 512; d += 256) { float x = row[d]; ss += x * x; }
        float tot = block_sum_256(ss);
        __shared__ float s_inv_k;
        if (threadIdx.x == 0) s_inv_k = rsqrtf(tot * (1.f / 512.f) + 1e-6f);
        __syncthreads();
        const float inv = s_inv_k;

        const float* cs = cosb + (size_t)r * 64;
        const float* sn = sinb + (size_t)r * 64;

        const int p = threadIdx.x;
        const int h = p >> 5, hdp = p & 31;
        float o2[2];
#pragma unroll
        for (int j = 0; j < 2; j++) {
            const int hd = 2 * hdp + j, d = h * 64 + hd;
            float val = row[d] * inv * kw[d];
            const int pd = (hd < 32) ? d + 32 : d - 32;
            float pv = row[pd] * inv * kw[pd];
            float rot = (hd < 32) ? -pv : pv;
            o2[j] = val * cs[hd] + rot * sn[hd];
        }
        const uint32_t hb = pack_hi(o2[0], o2[1]);
        const size_t oi = (((size_t)(b * NKV_ + h)) * 32 + hdp) * S_ + s;
        KH[oi] = hb;
        KL[oi] = pack_lo(o2[0], o2[1], hb);
    } else {
        const int i = (blk - 4096) * 256 + threadIdx.x;
        const int d  = i & 63;
        const int sp = (i >> 6) & 511;
        const int hk = (i >> 15) & 7;
        const int b  = i >> 18;
        const float x = vraw[((size_t)(b * 1024 + 2 * sp)) * 512 + hk * 64 + d];
        const float y = vraw[((size_t)(b * 1024 + 2 * sp + 1)) * 512 + hk * 64 + d];
        const uint32_t h = pack_hi(x, y);
        VH[i] = h;
        VL[i] = pack_lo(x, y, h);
    }
}

// ---------------------------------------------------------------------------
// GQA-paired flash: 2 sibling heads per CTA share K/V smem.
// 256 threads / 8 warps: warps 0-3 -> head 2*hp, warps 4-7 -> head 2*hp+1;
// each warp owns 16 query rows of its head (identical per-warp math to R12).
// Grid (hp=16, b=2, z=16), qt = 15 - z (LPT).
// ---------------------------------------------------------------------------
#define PP 36
#define BPP 72
#define KPLANE_W (32 * BPP)
#define FSTAGE_W (4 * KPLANE_W)
#define FSTAGE_B (FSTAGE_W * 4)
#define FLASH_SMEM (2 * FSTAGE_B + 2 * 128 * PP * 4)   // 110592 B

__global__ __launch_bounds__(256) void flash_bf16(
    const uint32_t* __restrict__ QH, const uint32_t* __restrict__ QL,
    const uint32_t* __restrict__ KH, const uint32_t* __restrict__ KL,
    const uint32_t* __restrict__ VH, const uint32_t* __restrict__ VL,
    float* __restrict__ ctx, float* __restrict__ mxC)
{
    extern __shared__ uint32_t fsm[];
    uint32_t* pH = fsm + 2 * FSTAGE_W;
    uint32_t* pL = pH + 128 * PP;

    const int tid = threadIdx.x, lane = tid & 31, warp = tid >> 5;
    const int g = lane >> 2, t = lane & 3;
    const int wm = (warp & 3) * 16;       // row block within the 64-query tile
    const int prow = warp * 16;           // P smem row base (128 rows)
    const int hp = blockIdx.x, b = blockIdx.y;
    const int qt = 15 - blockIdx.z;       // LPT
    const int head = 2 * hp + (warp >> 2);
    const int hk = hp >> 1;

    uint32_t sbase;
    asm("{ .reg .u64 tt; cvta.to.shared.u64 tt, %1; cvt.u32.u64 %0, tt; }"
        : "=r"(sbase) : "l"(fsm));

    const uint32_t* kbH = KH + ((size_t)(b * NKV_ + hk)) * 32 * S_;
    const uint32_t* kbL = KL + ((size_t)(b * NKV_ + hk)) * 32 * S_;
    const uint32_t* vbH = VH + ((size_t)(b * NKV_ + hk)) * 512 * 64;
    const uint32_t* vbL = VL + ((size_t)(b * NKV_ + hk)) * 512 * 64;

    uint32_t qa_h[4][4], qa_l[4][4];
    {
        const size_t qoff = (((size_t)(b * NH_ + head)) * S_ + qt * 64 + wm) * 32;
#pragma unroll
        for (int ks = 0; ks < 4; ks++) {
            qa_h[ks][0] = QH[qoff + g * 32 + ks * 8 + t];
            qa_h[ks][1] = QH[qoff + (g + 8) * 32 + ks * 8 + t];
            qa_h[ks][2] = QH[qoff + g * 32 + ks * 8 + t + 4];
            qa_h[ks][3] = QH[qoff + (g + 8) * 32 + ks * 8 + t + 4];
            qa_l[ks][0] = QL[qoff + g * 32 + ks * 8 + t];
            qa_l[ks][1] = QL[qoff + (g + 8) * 32 + ks * 8 + t];
            qa_l[ks][2] = QL[qoff + g * 32 + ks * 8 + t + 4];
            qa_l[ks][3] = QL[qoff + (g + 8) * 32 + ks * 8 + t + 4];
        }
    }

    float o[8][4];
#pragma unroll
    for (int nt = 0; nt < 8; nt++)
#pragma unroll
        for (int c = 0; c < 4; c++) o[nt][c] = 0.f;
    float m0 = -1e30f, m1 = -1e30f, l0 = 0.f, l1 = 0.f;

    const int ntiles = qt + 1;

    // tile loader: 2048 16B chunks over 4 planes, 8 per thread (256 threads)
    auto load_tile = [&](int kt) {
        const uint32_t st = sbase + (kt & 1) * FSTAGE_B;
#pragma unroll
        for (int i = 0; i < 8; i++) {
            const int plane = i >> 1;
            const int chunk = (i & 1) * 256 + tid;   // 0..511
            const int row = chunk >> 4;
            const int ch = chunk & 15;
            const uint32_t dst = st + plane * (KPLANE_W * 4) + row * (BPP * 4) + ch * 16;
            const uint32_t* src;
            if (plane == 0)      src = kbH + (size_t)row * S_ + kt * 64 + ch * 4;
            else if (plane == 1) src = kbL + (size_t)row * S_ + kt * 64 + ch * 4;
            else if (plane == 2) src = vbH + (size_t)(kt * 32 + row) * 64 + ch * 4;
            else                 src = vbL + (size_t)(kt * 32 + row) * 64 + ch * 4;
            cp16(dst, src);
        }
    };

    load_tile(0);
    asm volatile("cp.async.commit_group;" ::: "memory");

    for (int kt = 0; kt < ntiles; kt++) {
        if (kt + 1 < ntiles) load_tile(kt + 1);
        asm volatile("cp.async.commit_group;" ::: "memory");
        asm volatile("cp.async.wait_group 1;" ::: "memory");
        __syncthreads();

        const uint32_t* kThs = fsm + (kt & 1) * FSTAGE_W;
        const uint32_t* kTls = kThs + KPLANE_W;
        const uint32_t* vhs  = kThs + 2 * KPLANE_W;
        const uint32_t* vls  = kThs + 3 * KPLANE_W;

        float sf[8][4];
#pragma unroll
        for (int nt = 0; nt < 8; nt++)
#pragma unroll
            for (int c = 0; c < 4; c++) sf[nt][c] = 0.f;

#pragma unroll
        for (int nt = 0; nt < 8; nt++) {
#pragma unroll
            for (int ks = 0; ks < 4; ks++) {
                const uint32_t bh0 = kThs[(ks * 8 + t) * BPP + 8 * nt + g];
                const uint32_t bh1 = kThs[(ks * 8 + t + 4) * BPP + 8 * nt + g];
                const uint32_t bl0 = kTls[(ks * 8 + t) * BPP + 8 * nt + g];
                const uint32_t bl1 = kTls[(ks * 8 + t + 4) * BPP + 8 * nt + g];
                float* cc = sf[nt];
                mma_bf16(cc[0], cc[1], cc[2], cc[3],
                         qa_h[ks][0], qa_h[ks][1], qa_h[ks][2], qa_h[ks][3], bh0, bh1);
                mma_bf16(cc[0], cc[1], cc[2], cc[3],
                         qa_h[ks][0], qa_h[ks][1], qa_h[ks][2], qa_h[ks][3], bl0, bl1);
                mma_bf16(cc[0], cc[1], cc[2], cc[3],
                         qa_l[ks][0], qa_l[ks][1], qa_l[ks][2], qa_l[ks][3], bh0, bh1);
            }
        }

        const bool diag = (kt == qt);
        float mn0 = m0, mn1 = m1;
#pragma unroll
        for (int nt = 0; nt < 8; nt++) {
#pragma unroll
            for (int c = 0; c < 4; c++) {
                float v = sf[nt][c] * 0.125f;
                const int colloc = nt * 8 + 2 * t + (c & 1);
                const int rowloc = wm + g + ((c >= 2) ? 8 : 0);
                if (diag && colloc > rowloc) v = -1e30f;
                sf[nt][c] = v;
                if (c < 2) mn0 = fmaxf(mn0, v);
                else       mn1 = fmaxf(mn1, v);
            }
        }
        mn0 = fmaxf(mn0, __shfl_xor_sync(0xffffffffu, mn0, 1));
        mn0 = fmaxf(mn0, __shfl_xor_sync(0xffffffffu, mn0, 2));
        mn1 = fmaxf(mn1, __shfl_xor_sync(0xffffffffu, mn1, 1));
        mn1 = fmaxf(mn1, __shfl_xor_sync(0xffffffffu, mn1, 2));

        const float sc0 = __expf(m0 - mn0);
        const float sc1 = __expf(m1 - mn1);
        m0 = mn0; m1 = mn1;
        l0 *= sc0; l1 *= sc1;
#pragma unroll
        for (int nt = 0; nt < 8; nt++) {
            o[nt][0] *= sc0; o[nt][1] *= sc0;
            o[nt][2] *= sc1; o[nt][3] *= sc1;
        }

        float ps0 = 0.f, ps1 = 0.f;
#pragma unroll
        for (int nt = 0; nt < 8; nt++) {
            float p0 = __expf(sf[nt][0] - mn0);
            float p1 = __expf(sf[nt][1] - mn0);
            float p2 = __expf(sf[nt][2] - mn1);
            float p3 = __expf(sf[nt][3] - mn1);
            ps0 += p0 + p1;
            ps1 += p2 + p3;
            const uint32_t h01 = pack_hi(p0, p1);
            const uint32_t h23 = pack_hi(p2, p3);
            const int kp = nt * 4 + t;
            pH[(prow + g) * PP + kp] = h01;
            pH[(prow + g + 8) * PP + kp] = h23;
            pL[(prow + g) * PP + kp] = pack_lo(p0, p1, h01);
            pL[(prow + g + 8) * PP + kp] = pack_lo(p2, p3, h23);
        }
        ps0 += __shfl_xor_sync(0xffffffffu, ps0, 1);
        ps0 += __shfl_xor_sync(0xffffffffu, ps0, 2);
        ps1 += __shfl_xor_sync(0xffffffffu, ps1, 1);
        ps1 += __shfl_xor_sync(0xffffffffu, ps1, 2);
        l0 += ps0; l1 += ps1;
        __syncwarp();

#pragma unroll
        for (int ks = 0; ks < 4; ks++) {
            uint32_t pa_h[4], pa_l[4];
            pa_h[0] = pH[(prow + g) * PP + ks * 8 + t];
            pa_h[1] = pH[(prow + g + 8) * PP + ks * 8 + t];
            pa_h[2] = pH[(prow + g) * PP + ks * 8 + t + 4];
            pa_h[3] = pH[(prow + g + 8) * PP + ks * 8 + t + 4];
            pa_l[0] = pL[(prow + g) * PP + ks * 8 + t];
            pa_l[1] = pL[(prow + g + 8) * PP + ks * 8 + t];
            pa_l[2] = pL[(prow + g) * PP + ks * 8 + t + 4];
            pa_l[3] = pL[(prow + g + 8) * PP + ks * 8 + t + 4];
#pragma unroll
            for (int nt = 0; nt < 8; nt++) {
                const uint32_t bh0 = vhs[(ks * 8 + t) * BPP + 8 * nt + g];
                const uint32_t bh1 = vhs[(ks * 8 + t + 4) * BPP + 8 * nt + g];
                const uint32_t bl0 = vls[(ks * 8 + t) * BPP + 8 * nt + g];
                const uint32_t bl1 = vls[(ks * 8 + t + 4) * BPP + 8 * nt + g];
                float* cc = o[nt];
                mma_bf16(cc[0], cc[1], cc[2], cc[3],
                         pa_h[0], pa_h[1], pa_h[2], pa_h[3], bh0, bh1);
                mma_bf16(cc[0], cc[1], cc[2], cc[3],
                         pa_l[0], pa_l[1], pa_l[2], pa_l[3], bh0, bh1);
                mma_bf16(cc[0], cc[1], cc[2], cc[3],
                         pa_h[0], pa_h[1], pa_h[2], pa_h[3], bl0, bl1);
            }
        }
        __syncthreads();
    }

    // ---- epilogue: write ctx + fused row abs-max into mxC ----
    const float inv0 = 1.f / l0, inv1 = 1.f / l1;
    const int row0 = b * S_ + qt * 64 + wm + g;
    float* crow0 = ctx + (size_t)row0 * 2048 + head * 64;
    float* crow1 = crow0 + (size_t)8 * 2048;
    float mr0 = 0.f, mr1 = 0.f;
#pragma unroll
    for (int nt = 0; nt < 8; nt++) {
        const int col = nt * 8 + 2 * t;
        const float v0 = o[nt][0] * inv0, v1 = o[nt][1] * inv0;
        const float v2 = o[nt][2] * inv1, v3 = o[nt][3] * inv1;
        *reinterpret_cast<float2*>(crow0 + col) = make_float2(v0, v1);
        *reinterpret_cast<float2*>(crow1 + col) = make_float2(v2, v3);
        mr0 = fmaxf(mr0, fmaxf(fabsf(v0), fabsf(v1)));
        mr1 = fmaxf(mr1, fmaxf(fabsf(v2), fabsf(v3)));
    }
    mr0 = fmaxf(mr0, __shfl_xor_sync(0xffffffffu, mr0, 1));
    mr0 = fmaxf(mr0, __shfl_xor_sync(0xffffffffu, mr0, 2));
    mr1 = fmaxf(mr1, __shfl_xor_sync(0xffffffffu, mr1, 1));
    mr1 = fmaxf(mr1, __shfl_xor_sync(0xffffffffu, mr1, 2));
    if (t == 0) {
        atomicMax((unsigned int*)&mxC[row0],     __float_as_uint(mr0));
        atomicMax((unsigned int*)&mxC[row0 + 8], __float_as_uint(mr1));
    }
}

// ---------------------------------------------------------------------------
// Launch
// ---------------------------------------------------------------------------
extern "C" void kernel_launch(void* const* d_in, const int* in_sizes, int n_in,
                              void* d_out, int out_size)
{
    const float* X    = (const float*)d_in[0];
    const float* cosb = (const float*)d_in[1];
    const float* sinb = (const float*)d_in[2];
    // d_in[3] attention_mask unused (causal handled analytically)
    const float* wq = (const float*)d_in[4];
    const float* wk = (const float*)d_in[5];
    const float* wv = (const float*)d_in[6];
    const float* wo = (const float*)d_in[7];
    const float* qw = (const float*)d_in[8];
    const float* kw = (const float*)d_in[9];
    float* out = (float*)d_out;

    float *qraw, *kraw, *vraw, *ctx;
    uint32_t *QH, *QL, *KHp, *KLp, *VHp, *VLp;
    uint32_t *A1, *A2, *WQ1, *WQ2, *WK1, *WK2, *WV1, *WV2, *WO1, *WO2;
    float *mxA, *mxC, *mxQ, *mxK, *mxV, *mxO;
    cudaGetSymbolAddress((void**)&qraw, g_qraw);
    cudaGetSymbolAddress((void**)&kraw, g_kraw);
    cudaGetSymbolAddress((void**)&vraw, g_vraw);
    cudaGetSymbolAddress((void**)&ctx,  g_ctx);
    cudaGetSymbolAddress((void**)&QH,   g_QH);
    cudaGetSymbolAddress((void**)&QL,   g_QL);
    cudaGetSymbolAddress((void**)&KHp,  g_KHp);
    cudaGetSymbolAddress((void**)&KLp,  g_KLp);
    cudaGetSymbolAddress((void**)&VHp,  g_VHp);
    cudaGetSymbolAddress((void**)&VLp,  g_VLp);
    cudaGetSymbolAddress((void**)&A1,   g_A1);
    cudaGetSymbolAddress((void**)&A2,   g_A2);
    cudaGetSymbolAddress((void**)&WQ1,  g_WQ1);
    cudaGetSymbolAddress((void**)&WQ2,  g_WQ2);
    cudaGetSymbolAddress((void**)&WK1,  g_WK1);
    cudaGetSymbolAddress((void**)&WK2,  g_WK2);
    cudaGetSymbolAddress((void**)&WV1,  g_WV1);
    cudaGetSymbolAddress((void**)&WV2,  g_WV2);
    cudaGetSymbolAddress((void**)&WO1,  g_WO1);
    cudaGetSymbolAddress((void**)&WO2,  g_WO2);
    cudaGetSymbolAddress((void**)&mxA,  g_mxA);
    cudaGetSymbolAddress((void**)&mxC,  g_mxC);
    cudaGetSymbolAddress((void**)&mxQ,  g_mxQ);
    cudaGetSymbolAddress((void**)&mxK,  g_mxK);
    cudaGetSymbolAddress((void**)&mxV,  g_mxV);
    cudaGetSymbolAddress((void**)&mxO,  g_mxO);

    cudaFuncSetAttribute(flash_bf16, cudaFuncAttributeMaxDynamicSharedMemorySize,
                         FLASH_SMEM);
    cudaFuncSetAttribute(gemm_i8_qkv, cudaFuncAttributeMaxDynamicSharedMemorySize, G2_SMEM);
    cudaFuncSetAttribute(gemm_i8, cudaFuncAttributeMaxDynamicSharedMemorySize, G2_SMEM);

    // ---- scale + quant prep (R12, proven) ----
    zero_all<<<8, 256>>>(mxQ, mxK, mxV, mxO, mxC);
    colmax_all<<<dim3(80, 8), 256>>>(wq, wk, wv, wo, mxQ, mxK, mxV, mxO);
    quant_w_all<<<10240, 256>>>(wq, wk, wv, wo, mxQ, mxK, mxV, mxO,
                                WQ1, WQ2, WK1, WK2, WV1, WV2, WO1, WO2);
    rowmax<<<2048, 256>>>(X, mxA, 2048);
    tquant<<<dim3(64, 32), 256>>>(X, mxA, A1, A2, 2048, 2048);

    // ---- fused Q+K+V projections ----
    gemm_i8_qkv<<<dim3(24, 16), 256, G2_SMEM>>>(
        A1, A2, WQ1, WQ2, WK1, WK2, WV1, WV2,
        mxA, mxQ, mxK, mxV, qraw, kraw, vraw);

    // ---- fused norm / rope / pack ----
    normpack_all<<<6144, 256>>>(qraw, kraw, vraw, qw, kw, cosb, sinb,
                                QH, QL, KHp, KLp, VHp, VLp);

    // ---- GQA-paired flash (LPT) with fused ctx row-max ----
    flash_bf16<<<dim3(16, B_, 16), 256, FLASH_SMEM>>>(
        QH, QL, KHp, KLp, VHp, VLp, ctx, mxC);

    // ---- output projection (rowmax already done by flash) ----
    tquant<<<dim3(64, 32), 256>>>(ctx, mxC, A1, A2, 2048, 2048);
    gemm_i8<<<dim3(16, 16), 256, G2_SMEM>>>(A1, A2, WO1, WO2, mxC, mxO,
                                            out, 2048, 2048, 2048);
}

// round 14
// speedup vs baseline: 1.0358x; 1.0358x over previous
#include <cuda_runtime.h>
#include <cuda_bf16.h>
#include <cstdint>

// Problem constants
#define B_  2
#define S_  1024
#define H_  2048
#define NH_ 32
#define NKV_ 8
#define HD_ 64
#define M_  2048

// ---------------------------------------------------------------------------
// Scratch (device globals)
// ---------------------------------------------------------------------------
__device__ float g_qraw[M_ * 2048];
__device__ float g_kraw[M_ * 512];
__device__ float g_vraw[M_ * 512];
__device__ float g_ctx[M_ * 2048];
// flash packed bf16x2 operands
__device__ uint32_t g_QH[M_ * 1024], g_QL[M_ * 1024];
__device__ uint32_t g_KHp[524288],   g_KLp[524288];
__device__ uint32_t g_VHp[524288],   g_VLp[524288];
// int8 GEMM operands
__device__ uint32_t g_A1[512 * 2048], g_A2[512 * 2048];
__device__ uint32_t g_WQ1[512 * 2048], g_WQ2[512 * 2048];
__device__ uint32_t g_WK1[512 * 512],  g_WK2[512 * 512];
__device__ uint32_t g_WV1[512 * 512],  g_WV2[512 * 512];
__device__ uint32_t g_WO1[512 * 2048], g_WO2[512 * 2048];
// abs-max arrays
__device__ float g_mxA[2048];
__device__ float g_mxC[2048];
__device__ float g_mxQ[2048], g_mxK[512], g_mxV[512], g_mxO[2048];

// ---------------------------------------------------------------------------
// helpers
// ---------------------------------------------------------------------------
__device__ __forceinline__ void mma_bf16(
    float& c0, float& c1, float& c2, float& c3,
    uint32_t a0, uint32_t a1, uint32_t a2, uint32_t a3,
    uint32_t b0, uint32_t b1)
{
    asm volatile(
        "mma.sync.aligned.m16n8k16.row.col.f32.bf16.bf16.f32 "
        "{%0,%1,%2,%3}, {%4,%5,%6,%7}, {%8,%9}, {%0,%1,%2,%3};\n"
        : "+f"(c0), "+f"(c1), "+f"(c2), "+f"(c3)
        : "r"(a0), "r"(a1), "r"(a2), "r"(a3), "r"(b0), "r"(b1));
}

__device__ __forceinline__ void mma_s8(
    int& c0, int& c1, int& c2, int& c3,
    uint32_t a0, uint32_t a1, uint32_t a2, uint32_t a3,
    uint32_t b0, uint32_t b1)
{
    asm volatile(
        "mma.sync.aligned.m16n8k32.row.col.s32.s8.s8.s32 "
        "{%0,%1,%2,%3}, {%4,%5,%6,%7}, {%8,%9}, {%0,%1,%2,%3};\n"
        : "+r"(c0), "+r"(c1), "+r"(c2), "+r"(c3)
        : "r"(a0), "r"(a1), "r"(a2), "r"(a3), "r"(b0), "r"(b1));
}

__device__ __forceinline__ void cp16(uint32_t dst, const void* src) {
    asm volatile("cp.async.cg.shared.global [%0], [%1], 16;" :: "r"(dst), "l"(src));
}

__device__ __forceinline__ uint32_t pack_hi(float x, float y) {
    __nv_bfloat162 h = __floats2bfloat162_rn(x, y);
    return *reinterpret_cast<uint32_t*>(&h);
}
__device__ __forceinline__ uint32_t pack_lo(float x, float y, uint32_t hi) {
    __nv_bfloat162 h = *reinterpret_cast<__nv_bfloat162*>(&hi);
    float lx = x - __bfloat162float(h.x);
    float ly = y - __bfloat162float(h.y);
    __nv_bfloat162 l = __floats2bfloat162_rn(lx, ly);
    return *reinterpret_cast<uint32_t*>(&l);
}

__device__ __forceinline__ float quant_r127(float mx) {
    int e; frexpf(mx, &e);
    return 127.f * exp2f((float)(-e));
}
__device__ __forceinline__ float scl(float mx) {
    int e; frexpf(mx, &e);
    return exp2f((float)e) * (1.f / 127.f);
}
__device__ __forceinline__ void quant2(float x, float r127, int& q1, int& q2) {
    float a1 = rintf(x * r127);
    float r = fmaf(x, r127, -a1);
    float a2 = rintf(r * 256.f);
    a2 = fminf(fmaxf(a2, -127.f), 127.f);
    q1 = (int)a1; q2 = (int)a2;
}
__device__ __forceinline__ uint32_t pack4(int a, int b, int c, int d) {
    return (uint32_t)(a & 0xff) | ((uint32_t)(b & 0xff) << 8) |
           ((uint32_t)(c & 0xff) << 16) | ((uint32_t)(d & 0xff) << 24);
}

// ---------------------------------------------------------------------------
// reductions
// ---------------------------------------------------------------------------
__device__ __forceinline__ float block_sum_256(float v) {
    __shared__ float red[8];
#pragma unroll
    for (int o = 16; o > 0; o >>= 1) v += __shfl_xor_sync(0xffffffffu, v, o);
    const int lane = threadIdx.x & 31, wid = threadIdx.x >> 5;
    if (lane == 0) red[wid] = v;
    __syncthreads();
    float tot = 0.f;
    if (threadIdx.x < 8) tot = red[threadIdx.x];
#pragma unroll
    for (int o = 4; o > 0; o >>= 1) tot += __shfl_xor_sync(0xffffffffu, tot, o);
    return tot;
}

__device__ __forceinline__ float block_max_256(float v) {
    __shared__ float red[8];
#pragma unroll
    for (int o = 16; o > 0; o >>= 1) v = fmaxf(v, __shfl_xor_sync(0xffffffffu, v, o));
    const int lane = threadIdx.x & 31, wid = threadIdx.x >> 5;
    if (lane == 0) red[wid] = v;
    __syncthreads();
    float tot = 0.f;
    if (threadIdx.x < 8) tot = red[threadIdx.x];
#pragma unroll
    for (int o = 4; o > 0; o >>= 1) tot = fmaxf(tot, __shfl_xor_sync(0xffffffffu, tot, o));
    return tot;
}

// ---------------------------------------------------------------------------
// rowmax of X + fused zeroing of scale arrays (runs FIRST; stream-serial
// ordering guarantees zeros land before colmax_all's atomicMax).
// ---------------------------------------------------------------------------
__global__ __launch_bounds__(256) void rowmax_zero(
    const float* __restrict__ X, float* __restrict__ mx, int K,
    float* zq, float* zk, float* zv, float* zo, float* zc)
{
    const int r = blockIdx.x;
    if (r < 8) {
        const int i = r * 256 + threadIdx.x;
        zq[i] = 0.f; zo[i] = 0.f; zc[i] = 0.f;
        if (i < 512) { zk[i] = 0.f; zv[i] = 0.f; }
    }
    const float4* row = reinterpret_cast<const float4*>(X + (size_t)r * K);
    const int n4 = K >> 2;
    float v = 0.f;
    for (int k = threadIdx.x; k < n4; k += 256) {
        float4 x = row[k];
        v = fmaxf(v, fmaxf(fmaxf(fabsf(x.x), fabsf(x.y)),
                           fmaxf(fabsf(x.z), fabsf(x.w))));
    }
    float tot = block_max_256(v);
    if (threadIdx.x == 0) mx[r] = tot;
}

__global__ __launch_bounds__(256) void colmax_all(
    const float* __restrict__ wq, const float* __restrict__ wk,
    const float* __restrict__ wv, const float* __restrict__ wo,
    float* __restrict__ mxQ, float* __restrict__ mxK,
    float* __restrict__ mxV, float* __restrict__ mxO)
{
    __shared__ float s[4][64];
    int bx = blockIdx.x;
    const float* W; float* mx; int N;
    if (bx < 32)      { W = wq; mx = mxQ; N = 2048; }
    else if (bx < 40) { W = wk; mx = mxK; N = 512; bx -= 32; }
    else if (bx < 48) { W = wv; mx = mxV; N = 512; bx -= 40; }
    else              { W = wo; mx = mxO; N = 2048; bx -= 48; }
    const int n0 = bx * 64, k0 = blockIdx.y * 256;
    const int c = threadIdx.x & 63, r = threadIdx.x >> 6;
    float v = 0.f;
#pragma unroll 8
    for (int j = 0; j < 64; j++)
        v = fmaxf(v, fabsf(W[(size_t)(k0 + 4 * j + r) * N + n0 + c]));
    s[r][c] = v;
    __syncthreads();
    if (r == 0) {
        float m = fmaxf(fmaxf(s[0][c], s[1][c]), fmaxf(s[2][c], s[3][c]));
        atomicMax((unsigned int*)&mx[n0 + c], __float_as_uint(m));
    }
}

__global__ __launch_bounds__(256) void quant_w_all(
    const float* __restrict__ wq, const float* __restrict__ wk,
    const float* __restrict__ wv, const float* __restrict__ wo,
    const float* __restrict__ mxQ, const float* __restrict__ mxK,
    const float* __restrict__ mxV, const float* __restrict__ mxO,
    uint32_t* __restrict__ WQ1, uint32_t* __restrict__ WQ2,
    uint32_t* __restrict__ WK1, uint32_t* __restrict__ WK2,
    uint32_t* __restrict__ WV1, uint32_t* __restrict__ WV2,
    uint32_t* __restrict__ WO1, uint32_t* __restrict__ WO2)
{
    int i = blockIdx.x * 256 + threadIdx.x;
    const float* W; const float* mx; uint32_t *B1, *B2; int N;
    if (i < 1048576)      { W = wq; mx = mxQ; B1 = WQ1; B2 = WQ2; N = 2048; }
    else if (i < 1310720) { W = wk; mx = mxK; B1 = WK1; B2 = WK2; N = 512; i -= 1048576; }
    else if (i < 1572864) { W = wv; mx = mxV; B1 = WV1; B2 = WV2; N = 512; i -= 1310720; }
    else                  { W = wo; mx = mxO; B1 = WO1; B2 = WO2; N = 2048; i -= 1572864; }
    const int kq = i / N, n = i - kq * N;
    const float r127 = quant_r127(mx[n]);
    int q1[4], q2[4];
#pragma unroll
    for (int j = 0; j < 4; j++)
        quant2(W[(size_t)(4 * kq + j) * N + n], r127, q1[j], q2[j]);
    B1[i] = pack4(q1[0], q1[1], q1[2], q1[3]);
    B2[i] = pack4(q2[0], q2[1], q2[2], q2[3]);
}

__global__ __launch_bounds__(256) void tquant(
    const float* __restrict__ X, const float* __restrict__ mxRow,
    uint32_t* __restrict__ A1, uint32_t* __restrict__ A2, int M, int K)
{
    __shared__ float t[64][33];
    const int m0 = blockIdx.x * 32, k0 = blockIdx.y * 64;
#pragma unroll
    for (int i = threadIdx.x; i < 32 * 64; i += 256) {
        const int ml = i >> 6, kl = i & 63;
        t[kl][ml] = X[(size_t)(m0 + ml) * K + k0 + kl];
    }
    __syncthreads();
#pragma unroll
    for (int i = threadIdx.x; i < 32 * 16; i += 256) {
        const int kql = i >> 5, ml = i & 31;
        const float r127 = quant_r127(mxRow[m0 + ml]);
        int q1[4], q2[4];
#pragma unroll
        for (int j = 0; j < 4; j++)
            quant2(t[4 * kql + j][ml], r127, q1[j], q2[j]);
        const size_t o = (size_t)(k0 / 4 + kql) * M + m0 + ml;
        A1[o] = pack4(q1[0], q1[1], q1[2], q1[3]);
        A2[o] = pack4(q2[0], q2[1], q2[2], q2[3]);
    }
}

// ---------------------------------------------------------------------------
// int8 split GEMM body (R9, proven)
// ---------------------------------------------------------------------------
#define KPT 8
#define PITCH 132
#define PLANE_W (KPT * PITCH)
#define STG_W (4 * PLANE_W)
#define STG_BYTES (STG_W * 4)
#define G2_SMEM (4 * STG_BYTES)

__device__ __forceinline__ void gemm_i8_body(
    const uint32_t* __restrict__ A1g, const uint32_t* __restrict__ A2g,
    const uint32_t* __restrict__ B1g, const uint32_t* __restrict__ B2g,
    const float* __restrict__ mxRow, const float* __restrict__ mxCol,
    float* __restrict__ C, int AM, int N, int K, int brow, int bcol)
{
    extern __shared__ uint32_t sm2[];

    const int tid  = threadIdx.x;
    const int lane = tid & 31;
    const int warp = tid >> 5;
    const int gid  = lane >> 2;
    const int tig  = lane & 3;
    const int wm   = (warp & 3) * 32;
    const int wn   = (warp >> 2) * 64;

    uint32_t sbase;
    asm("{ .reg .u64 t; cvta.to.shared.u64 t, %1; cvt.u32.u64 %0, t; }"
        : "=r"(sbase) : "l"(sm2));

    const int NK = K >> 5;
    const int l_row = tid >> 5;
    const int l_ch  = tid & 31;

    auto load_stage = [&](int kt) {
        const uint32_t st = sbase + (kt & 3) * STG_BYTES;
        const size_t kqg = (size_t)(kt * KPT + l_row);
        const size_t aoff = kqg * AM + brow + l_ch * 4;
        const size_t boff = kqg * N + bcol + l_ch * 4;
        const uint32_t d0 = st + l_row * (PITCH * 4) + l_ch * 16;
        cp16(d0,                       A1g + aoff);
        cp16(d0 + PLANE_W * 4,         A2g + aoff);
        cp16(d0 + 2 * (PLANE_W * 4),   B1g + boff);
        cp16(d0 + 3 * (PLANE_W * 4),   B2g + boff);
    };

    int c1[2][8][4], c2[2][8][4];
#pragma unroll
    for (int i = 0; i < 2; i++)
#pragma unroll
        for (int j = 0; j < 8; j++)
#pragma unroll
            for (int v = 0; v < 4; v++) { c1[i][j][v] = 0; c2[i][j][v] = 0; }

    load_stage(0);
    asm volatile("cp.async.commit_group;" ::: "memory");
    load_stage(1);
    asm volatile("cp.async.commit_group;" ::: "memory");
    load_stage(2);
    asm volatile("cp.async.commit_group;" ::: "memory");

    for (int kt = 0; kt < NK; kt++) {
        asm volatile("cp.async.wait_group 2;" ::: "memory");
        __syncthreads();

        const uint32_t* A1s = sm2 + (kt & 3) * STG_W;
        const uint32_t* A2s = A1s + PLANE_W;
        const uint32_t* B1s = A1s + 2 * PLANE_W;
        const uint32_t* B2s = A1s + 3 * PLANE_W;

        uint32_t a1f[2][4], a2f[2][4];
#pragma unroll
        for (int mt = 0; mt < 2; mt++) {
            const int m0 = wm + mt * 16 + gid;
            a1f[mt][0] = A1s[tig * PITCH + m0];
            a1f[mt][1] = A1s[tig * PITCH + m0 + 8];
            a1f[mt][2] = A1s[(tig + 4) * PITCH + m0];
            a1f[mt][3] = A1s[(tig + 4) * PITCH + m0 + 8];
            a2f[mt][0] = A2s[tig * PITCH + m0];
            a2f[mt][1] = A2s[tig * PITCH + m0 + 8];
            a2f[mt][2] = A2s[(tig + 4) * PITCH + m0];
            a2f[mt][3] = A2s[(tig + 4) * PITCH + m0 + 8];
        }
#pragma unroll
        for (int nt = 0; nt < 8; nt++) {
            const int n0 = wn + nt * 8 + gid;
            const uint32_t b10 = B1s[tig * PITCH + n0];
            const uint32_t b11 = B1s[(tig + 4) * PITCH + n0];
            const uint32_t b20 = B2s[tig * PITCH + n0];
            const uint32_t b21 = B2s[(tig + 4) * PITCH + n0];
#pragma unroll
            for (int mt = 0; mt < 2; mt++) {
                int* p1 = c1[mt][nt];
                int* p2 = c2[mt][nt];
                mma_s8(p1[0], p1[1], p1[2], p1[3],
                       a1f[mt][0], a1f[mt][1], a1f[mt][2], a1f[mt][3], b10, b11);
                mma_s8(p2[0], p2[1], p2[2], p2[3],
                       a1f[mt][0], a1f[mt][1], a1f[mt][2], a1f[mt][3], b20, b21);
                mma_s8(p2[0], p2[1], p2[2], p2[3],
                       a2f[mt][0], a2f[mt][1], a2f[mt][2], a2f[mt][3], b10, b11);
            }
        }

        __syncthreads();
        if (kt + 3 < NK) load_stage(kt + 3);
        asm volatile("cp.async.commit_group;" ::: "memory");
    }

#pragma unroll
    for (int mt = 0; mt < 2; mt++) {
        const int r0 = brow + wm + mt * 16 + gid;
        const float sr0 = scl(mxRow[r0]);
        const float sr1 = scl(mxRow[r0 + 8]);
#pragma unroll
        for (int nt = 0; nt < 8; nt++) {
            const int col = bcol + wn + nt * 8 + 2 * tig;
            const float sc0 = scl(mxCol[col]);
            const float sc1 = scl(mxCol[col + 1]);
            const int* p1 = c1[mt][nt];
            const int* p2 = c2[mt][nt];
            const float v0 = (float)p1[0] + (float)p2[0] * (1.f / 256.f);
            const float v1 = (float)p1[1] + (float)p2[1] * (1.f / 256.f);
            const float v2 = (float)p1[2] + (float)p2[2] * (1.f / 256.f);
            const float v3 = (float)p1[3] + (float)p2[3] * (1.f / 256.f);
            *reinterpret_cast<float2*>(C + (size_t)r0 * N + col) =
                make_float2(sr0 * sc0 * v0, sr0 * sc1 * v1);
            *reinterpret_cast<float2*>(C + (size_t)(r0 + 8) * N + col) =
                make_float2(sr1 * sc0 * v2, sr1 * sc1 * v3);
        }
    }
}

__global__ __launch_bounds__(256) void gemm_i8_qkv(
    const uint32_t* __restrict__ A1g, const uint32_t* __restrict__ A2g,
    const uint32_t* __restrict__ Q1g, const uint32_t* __restrict__ Q2g,
    const uint32_t* __restrict__ K1g, const uint32_t* __restrict__ K2g,
    const uint32_t* __restrict__ V1g, const uint32_t* __restrict__ V2g,
    const float* __restrict__ mxRow,
    const float* __restrict__ mxQ, const float* __restrict__ mxK,
    const float* __restrict__ mxV,
    float* __restrict__ Cq, float* __restrict__ Ck, float* __restrict__ Cv)
{
    const int x = blockIdx.x;
    if (x < 16) {
        gemm_i8_body(A1g, A2g, Q1g, Q2g, mxRow, mxQ, Cq, 2048, 2048, 2048,
                     blockIdx.y * 128, x * 128);
    } else {
        const int xx = x - 16;
        const bool isv = xx >= 4;
        const int bx = xx & 3;
        gemm_i8_body(A1g, A2g, isv ? V1g : K1g, isv ? V2g : K2g,
                     mxRow, isv ? mxV : mxK, isv ? Cv : Ck,
                     2048, 512, 2048, blockIdx.y * 128, bx * 128);
    }
}

__global__ __launch_bounds__(256) void gemm_i8(
    const uint32_t* __restrict__ A1g, const uint32_t* __restrict__ A2g,
    const uint32_t* __restrict__ B1g, const uint32_t* __restrict__ B2g,
    const float* __restrict__ mxRow, const float* __restrict__ mxCol,
    float* __restrict__ C, int AM, int N, int K)
{
    gemm_i8_body(A1g, A2g, B1g, B2g, mxRow, mxCol, C, AM, N, K,
                 blockIdx.y * 128, blockIdx.x * 128);
}

// ---------------------------------------------------------------------------
// Fused norm/rope/pack (R10, proven): grid 6144
// ---------------------------------------------------------------------------
__global__ __launch_bounds__(256) void normpack_all(
    const float* __restrict__ qraw, const float* __restrict__ kraw,
    const float* __restrict__ vraw,
    const float* __restrict__ qw, const float* __restrict__ kw,
    const float* __restrict__ cosb, const float* __restrict__ sinb,
    uint32_t* __restrict__ QH, uint32_t* __restrict__ QL,
    uint32_t* __restrict__ KH, uint32_t* __restrict__ KL,
    uint32_t* __restrict__ VH, uint32_t* __restrict__ VL)
{
    const int blk = blockIdx.x;
    if (blk < 2048) {
        const int r = blk;
        const int b = r >> 10, s = r & 1023;
        const float* row = qraw + (size_t)r * 2048;

        float ss = 0.f;
        for (int d = threadIdx.x; d < 2048; d += 256) { float x = row[d]; ss += x * x; }
        float tot = block_sum_256(ss);
        __shared__ float s_inv_q;
        if (threadIdx.x == 0) s_inv_q = rsqrtf(tot * (1.f / 2048.f) + 1e-6f);
        __syncthreads();
        const float inv = s_inv_q;

        const float* cs = cosb + (size_t)r * 64;
        const float* sn = sinb + (size_t)r * 64;

        for (int p = threadIdx.x; p < 1024; p += 256) {
            const int h = p >> 5, hdp = p & 31;
            float o2[2];
#pragma unroll
            for (int j = 0; j < 2; j++) {
                const int hd = 2 * hdp + j, d = h * 64 + hd;
                float val = row[d] * inv * qw[d];
                const int pd = (hd < 32) ? d + 32 : d - 32;
                float pv = row[pd] * inv * qw[pd];
                float rot = (hd < 32) ? -pv : pv;
                o2[j] = val * cs[hd] + rot * sn[hd];
            }
            const uint32_t hb = pack_hi(o2[0], o2[1]);
            const size_t oi = (((size_t)(b * NH_ + h)) * S_ + s) * 32 + hdp;
            QH[oi] = hb;
            QL[oi] = pack_lo(o2[0], o2[1], hb);
        }
    } else if (blk < 4096) {
        const int r = blk - 2048;
        const int b = r >> 10, s = r & 1023;
        const float* row = kraw + (size_t)r * 512;

        float ss = 0.f;
        for (int d = threadIdx.x; d < 512; d += 256) { float x = row[d]; ss += x * x; }
        float tot = block_sum_256(ss);
        __shared__ float s_inv_k;
        if (threadIdx.x == 0) s_inv_k = rsqrtf(tot * (1.f / 512.f) + 1e-6f);
        __syncthreads();
        const float inv = s_inv_k;

        const float* cs = cosb + (size_t)r * 64;
        const float* sn = sinb + (size_t)r * 64;

        const int p = threadIdx.x;
        const int h = p >> 5, hdp = p & 31;
        float o2[2];
#pragma unroll
        for (int j = 0; j < 2; j++) {
            const int hd = 2 * hdp + j, d = h * 64 + hd;
            float val = row[d] * inv * kw[d];
            const int pd = (hd < 32) ? d + 32 : d - 32;
            float pv = row[pd] * inv * kw[pd];
            float rot = (hd < 32) ? -pv : pv;
            o2[j] = val * cs[hd] + rot * sn[hd];
        }
        const uint32_t hb = pack_hi(o2[0], o2[1]);
        const size_t oi = (((size_t)(b * NKV_ + h)) * 32 + hdp) * S_ + s;
        KH[oi] = hb;
        KL[oi] = pack_lo(o2[0], o2[1], hb);
    } else {
        const int i = (blk - 4096) * 256 + threadIdx.x;
        const int d  = i & 63;
        const int sp = (i >> 6) & 511;
        const int hk = (i >> 15) & 7;
        const int b  = i >> 18;
        const float x = vraw[((size_t)(b * 1024 + 2 * sp)) * 512 + hk * 64 + d];
        const float y = vraw[((size_t)(b * 1024 + 2 * sp + 1)) * 512 + hk * 64 + d];
        const uint32_t h = pack_hi(x, y);
        VH[i] = h;
        VL[i] = pack_lo(x, y, h);
    }
}

// ---------------------------------------------------------------------------
// Flash attention (R12, proven): 128 threads, per-head, LPT, fused ctx rowmax.
// Grid (h=32, b=2, z=16), qt = 15 - z.
// ---------------------------------------------------------------------------
#define PP 36
#define BPP 72
#define KPLANE_W (32 * BPP)
#define FSTAGE_W (4 * KPLANE_W)
#define FSTAGE_B (FSTAGE_W * 4)
#define FLASH_SMEM (2 * FSTAGE_B + 2 * 64 * PP * 4)

__global__ __launch_bounds__(128) void flash_bf16(
    const uint32_t* __restrict__ QH, const uint32_t* __restrict__ QL,
    const uint32_t* __restrict__ KH, const uint32_t* __restrict__ KL,
    const uint32_t* __restrict__ VH, const uint32_t* __restrict__ VL,
    float* __restrict__ ctx, float* __restrict__ mxC)
{
    extern __shared__ uint32_t fsm[];
    uint32_t* pH = fsm + 2 * FSTAGE_W;
    uint32_t* pL = pH + 64 * PP;

    const int tid = threadIdx.x, lane = tid & 31, warp = tid >> 5;
    const int g = lane >> 2, t = lane & 3;
    const int wm = warp * 16;
    const int h = blockIdx.x, b = blockIdx.y;
    const int qt = 15 - blockIdx.z;
    const int hk = h >> 2;

    uint32_t sbase;
    asm("{ .reg .u64 tt; cvta.to.shared.u64 tt, %1; cvt.u32.u64 %0, tt; }"
        : "=r"(sbase) : "l"(fsm));

    const uint32_t* kbH = KH + ((size_t)(b * NKV_ + hk)) * 32 * S_;
    const uint32_t* kbL = KL + ((size_t)(b * NKV_ + hk)) * 32 * S_;
    const uint32_t* vbH = VH + ((size_t)(b * NKV_ + hk)) * 512 * 64;
    const uint32_t* vbL = VL + ((size_t)(b * NKV_ + hk)) * 512 * 64;

    uint32_t qa_h[4][4], qa_l[4][4];
    {
        const size_t qoff = (((size_t)(b * NH_ + h)) * S_ + qt * 64 + wm) * 32;
#pragma unroll
        for (int ks = 0; ks < 4; ks++) {
            qa_h[ks][0] = QH[qoff + g * 32 + ks * 8 + t];
            qa_h[ks][1] = QH[qoff + (g + 8) * 32 + ks * 8 + t];
            qa_h[ks][2] = QH[qoff + g * 32 + ks * 8 + t + 4];
            qa_h[ks][3] = QH[qoff + (g + 8) * 32 + ks * 8 + t + 4];
            qa_l[ks][0] = QL[qoff + g * 32 + ks * 8 + t];
            qa_l[ks][1] = QL[qoff + (g + 8) * 32 + ks * 8 + t];
            qa_l[ks][2] = QL[qoff + g * 32 + ks * 8 + t + 4];
            qa_l[ks][3] = QL[qoff + (g + 8) * 32 + ks * 8 + t + 4];
        }
    }

    float o[8][4];
#pragma unroll
    for (int nt = 0; nt < 8; nt++)
#pragma unroll
        for (int c = 0; c < 4; c++) o[nt][c] = 0.f;
    float m0 = -1e30f, m1 = -1e30f, l0 = 0.f, l1 = 0.f;

    const int ntiles = qt + 1;

    auto load_tile = [&](int kt) {
        const uint32_t st = sbase + (kt & 1) * FSTAGE_B;
#pragma unroll
        for (int i = 0; i < 16; i++) {
            const int plane = i >> 2;
            const int chunk = (i & 3) * 128 + tid;
            const int row = chunk >> 4;
            const int ch = chunk & 15;
            const uint32_t dst = st + plane * (KPLANE_W * 4) + row * (BPP * 4) + ch * 16;
            const uint32_t* src;
            if (plane == 0)      src = kbH + (size_t)row * S_ + kt * 64 + ch * 4;
            else if (plane == 1) src = kbL + (size_t)row * S_ + kt * 64 + ch * 4;
            else if (plane == 2) src = vbH + (size_t)(kt * 32 + row) * 64 + ch * 4;
            else                 src = vbL + (size_t)(kt * 32 + row) * 64 + ch * 4;
            cp16(dst, src);
        }
    };

    load_tile(0);
    asm volatile("cp.async.commit_group;" ::: "memory");

    for (int kt = 0; kt < ntiles; kt++) {
        if (kt + 1 < ntiles) load_tile(kt + 1);
        asm volatile("cp.async.commit_group;" ::: "memory");
        asm volatile("cp.async.wait_group 1;" ::: "memory");
        __syncthreads();

        const uint32_t* kThs = fsm + (kt & 1) * FSTAGE_W;
        const uint32_t* kTls = kThs + KPLANE_W;
        const uint32_t* vhs  = kThs + 2 * KPLANE_W;
        const uint32_t* vls  = kThs + 3 * KPLANE_W;

        float sf[8][4];
#pragma unroll
        for (int nt = 0; nt < 8; nt++)
#pragma unroll
            for (int c = 0; c < 4; c++) sf[nt][c] = 0.f;

#pragma unroll
        for (int nt = 0; nt < 8; nt++) {
#pragma unroll
            for (int ks = 0; ks < 4; ks++) {
                const uint32_t bh0 = kThs[(ks * 8 + t) * BPP + 8 * nt + g];
                const uint32_t bh1 = kThs[(ks * 8 + t + 4) * BPP + 8 * nt + g];
                const uint32_t bl0 = kTls[(ks * 8 + t) * BPP + 8 * nt + g];
                const uint32_t bl1 = kTls[(ks * 8 + t + 4) * BPP + 8 * nt + g];
                float* cc = sf[nt];
                mma_bf16(cc[0], cc[1], cc[2], cc[3],
                         qa_h[ks][0], qa_h[ks][1], qa_h[ks][2], qa_h[ks][3], bh0, bh1);
                mma_bf16(cc[0], cc[1], cc[2], cc[3],
                         qa_h[ks][0], qa_h[ks][1], qa_h[ks][2], qa_h[ks][3], bl0, bl1);
                mma_bf16(cc[0], cc[1], cc[2], cc[3],
                         qa_l[ks][0], qa_l[ks][1], qa_l[ks][2], qa_l[ks][3], bh0, bh1);
            }
        }

        const bool diag = (kt == qt);
        float mn0 = m0, mn1 = m1;
#pragma unroll
        for (int nt = 0; nt < 8; nt++) {
#pragma unroll
            for (int c = 0; c < 4; c++) {
                float v = sf[nt][c] * 0.125f;
                const int colloc = nt * 8 + 2 * t + (c & 1);
                const int rowloc = wm + g + ((c >= 2) ? 8 : 0);
                if (diag && colloc > rowloc) v = -1e30f;
                sf[nt][c] = v;
                if (c < 2) mn0 = fmaxf(mn0, v);
                else       mn1 = fmaxf(mn1, v);
            }
        }
        mn0 = fmaxf(mn0, __shfl_xor_sync(0xffffffffu, mn0, 1));
        mn0 = fmaxf(mn0, __shfl_xor_sync(0xffffffffu, mn0, 2));
        mn1 = fmaxf(mn1, __shfl_xor_sync(0xffffffffu, mn1, 1));
        mn1 = fmaxf(mn1, __shfl_xor_sync(0xffffffffu, mn1, 2));

        const float sc0 = __expf(m0 - mn0);
        const float sc1 = __expf(m1 - mn1);
        m0 = mn0; m1 = mn1;
        l0 *= sc0; l1 *= sc1;
#pragma unroll
        for (int nt = 0; nt < 8; nt++) {
            o[nt][0] *= sc0; o[nt][1] *= sc0;
            o[nt][2] *= sc1; o[nt][3] *= sc1;
        }

        float ps0 = 0.f, ps1 = 0.f;
#pragma unroll
        for (int nt = 0; nt < 8; nt++) {
            float p0 = __expf(sf[nt][0] - mn0);
            float p1 = __expf(sf[nt][1] - mn0);
            float p2 = __expf(sf[nt][2] - mn1);
            float p3 = __expf(sf[nt][3] - mn1);
            ps0 += p0 + p1;
            ps1 += p2 + p3;
            const uint32_t h01 = pack_hi(p0, p1);
            const uint32_t h23 = pack_hi(p2, p3);
            const int kp = nt * 4 + t;
            pH[(wm + g) * PP + kp] = h01;
            pH[(wm + g + 8) * PP + kp] = h23;
            pL[(wm + g) * PP + kp] = pack_lo(p0, p1, h01);
            pL[(wm + g + 8) * PP + kp] = pack_lo(p2, p3, h23);
        }
        ps0 += __shfl_xor_sync(0xffffffffu, ps0, 1);
        ps0 += __shfl_xor_sync(0xffffffffu, ps0, 2);
        ps1 += __shfl_xor_sync(0xffffffffu, ps1, 1);
        ps1 += __shfl_xor_sync(0xffffffffu, ps1, 2);
        l0 += ps0; l1 += ps1;
        __syncwarp();

#pragma unroll
        for (int ks = 0; ks < 4; ks++) {
            uint32_t pa_h[4], pa_l[4];
            pa_h[0] = pH[(wm + g) * PP + ks * 8 + t];
            pa_h[1] = pH[(wm + g + 8) * PP + ks * 8 + t];
            pa_h[2] = pH[(wm + g) * PP + ks * 8 + t + 4];
            pa_h[3] = pH[(wm + g + 8) * PP + ks * 8 + t + 4];
            pa_l[0] = pL[(wm + g) * PP + ks * 8 + t];
            pa_l[1] = pL[(wm + g + 8) * PP + ks * 8 + t];
            pa_l[2] = pL[(wm + g) * PP + ks * 8 + t + 4];
            pa_l[3] = pL[(wm + g + 8) * PP + ks * 8 + t + 4];
#pragma unroll
            for (int nt = 0; nt < 8; nt++) {
                const uint32_t bh0 = vhs[(ks * 8 + t) * BPP + 8 * nt + g];
                const uint32_t bh1 = vhs[(ks * 8 + t + 4) * BPP + 8 * nt + g];
                const uint32_t bl0 = vls[(ks * 8 + t) * BPP + 8 * nt + g];
                const uint32_t bl1 = vls[(ks * 8 + t + 4) * BPP + 8 * nt + g];
                float* cc = o[nt];
                mma_bf16(cc[0], cc[1], cc[2], cc[3],
                         pa_h[0], pa_h[1], pa_h[2], pa_h[3], bh0, bh1);
                mma_bf16(cc[0], cc[1], cc[2], cc[3],
                         pa_l[0], pa_l[1], pa_l[2], pa_l[3], bh0, bh1);
                mma_bf16(cc[0], cc[1], cc[2], cc[3],
                         pa_h[0], pa_h[1], pa_h[2], pa_h[3], bl0, bl1);
            }
        }
        __syncthreads();
    }

    // ---- epilogue: write ctx + fused row abs-max into mxC ----
    const float inv0 = 1.f / l0, inv1 = 1.f / l1;
    const int row0 = b * S_ + qt * 64 + wm + g;
    float* crow0 = ctx + (size_t)row0 * 2048 + h * 64;
    float* crow1 = crow0 + (size_t)8 * 2048;
    float mr0 = 0.f, mr1 = 0.f;
#pragma unroll
    for (int nt = 0; nt < 8; nt++) {
        const int col = nt * 8 + 2 * t;
        const float v0 = o[nt][0] * inv0, v1 = o[nt][1] * inv0;
        const float v2 = o[nt][2] * inv1, v3 = o[nt][3] * inv1;
        *reinterpret_cast<float2*>(crow0 + col) = make_float2(v0, v1);
        *reinterpret_cast<float2*>(crow1 + col) = make_float2(v2, v3);
        mr0 = fmaxf(mr0, fmaxf(fabsf(v0), fabsf(v1)));
        mr1 = fmaxf(mr1, fmaxf(fabsf(v2), fabsf(v3)));
    }
    mr0 = fmaxf(mr0, __shfl_xor_sync(0xffffffffu, mr0, 1));
    mr0 = fmaxf(mr0, __shfl_xor_sync(0xffffffffu, mr0, 2));
    mr1 = fmaxf(mr1, __shfl_xor_sync(0xffffffffu, mr1, 1));
    mr1 = fmaxf(mr1, __shfl_xor_sync(0xffffffffu, mr1, 2));
    if (t == 0) {
        atomicMax((unsigned int*)&mxC[row0],     __float_as_uint(mr0));
        atomicMax((unsigned int*)&mxC[row0 + 8], __float_as_uint(mr1));
    }
}

// ---------------------------------------------------------------------------
// Launch
// ---------------------------------------------------------------------------
extern "C" void kernel_launch(void* const* d_in, const int* in_sizes, int n_in,
                              void* d_out, int out_size)
{
    const float* X    = (const float*)d_in[0];
    const float* cosb = (const float*)d_in[1];
    const float* sinb = (const float*)d_in[2];
    // d_in[3] attention_mask unused (causal handled analytically)
    const float* wq = (const float*)d_in[4];
    const float* wk = (const float*)d_in[5];
    const float* wv = (const float*)d_in[6];
    const float* wo = (const float*)d_in[7];
    const float* qw = (const float*)d_in[8];
    const float* kw = (const float*)d_in[9];
    float* out = (float*)d_out;

    float *qraw, *kraw, *vraw, *ctx;
    uint32_t *QH, *QL, *KHp, *KLp, *VHp, *VLp;
    uint32_t *A1, *A2, *WQ1, *WQ2, *WK1, *WK2, *WV1, *WV2, *WO1, *WO2;
    float *mxA, *mxC, *mxQ, *mxK, *mxV, *mxO;
    cudaGetSymbolAddress((void**)&qraw, g_qraw);
    cudaGetSymbolAddress((void**)&kraw, g_kraw);
    cudaGetSymbolAddress((void**)&vraw, g_vraw);
    cudaGetSymbolAddress((void**)&ctx,  g_ctx);
    cudaGetSymbolAddress((void**)&QH,   g_QH);
    cudaGetSymbolAddress((void**)&QL,   g_QL);
    cudaGetSymbolAddress((void**)&KHp,  g_KHp);
    cudaGetSymbolAddress((void**)&KLp,  g_KLp);
    cudaGetSymbolAddress((void**)&VHp,  g_VHp);
    cudaGetSymbolAddress((void**)&VLp,  g_VLp);
    cudaGetSymbolAddress((void**)&A1,   g_A1);
    cudaGetSymbolAddress((void**)&A2,   g_A2);
    cudaGetSymbolAddress((void**)&WQ1,  g_WQ1);
    cudaGetSymbolAddress((void**)&WQ2,  g_WQ2);
    cudaGetSymbolAddress((void**)&WK1,  g_WK1);
    cudaGetSymbolAddress((void**)&WK2,  g_WK2);
    cudaGetSymbolAddress((void**)&WV1,  g_WV1);
    cudaGetSymbolAddress((void**)&WV2,  g_WV2);
    cudaGetSymbolAddress((void**)&WO1,  g_WO1);
    cudaGetSymbolAddress((void**)&WO2,  g_WO2);
    cudaGetSymbolAddress((void**)&mxA,  g_mxA);
    cudaGetSymbolAddress((void**)&mxC,  g_mxC);
    cudaGetSymbolAddress((void**)&mxQ,  g_mxQ);
    cudaGetSymbolAddress((void**)&mxK,  g_mxK);
    cudaGetSymbolAddress((void**)&mxV,  g_mxV);
    cudaGetSymbolAddress((void**)&mxO,  g_mxO);

    cudaFuncSetAttribute(flash_bf16, cudaFuncAttributeMaxDynamicSharedMemorySize,
                         FLASH_SMEM);
    cudaFuncSetAttribute(gemm_i8_qkv, cudaFuncAttributeMaxDynamicSharedMemorySize, G2_SMEM);
    cudaFuncSetAttribute(gemm_i8, cudaFuncAttributeMaxDynamicSharedMemorySize, G2_SMEM);

    // ---- prep: rowmax(X) with fused zeroing, then weight colmax+quant ----
    rowmax_zero<<<2048, 256>>>(X, mxA, 2048, mxQ, mxK, mxV, mxO, mxC);
    colmax_all<<<dim3(80, 8), 256>>>(wq, wk, wv, wo, mxQ, mxK, mxV, mxO);
    quant_w_all<<<10240, 256>>>(wq, wk, wv, wo, mxQ, mxK, mxV, mxO,
                                WQ1, WQ2, WK1, WK2, WV1, WV2, WO1, WO2);
    tquant<<<dim3(64, 32), 256>>>(X, mxA, A1, A2, 2048, 2048);

    // ---- fused Q+K+V projections ----
    gemm_i8_qkv<<<dim3(24, 16), 256, G2_SMEM>>>(
        A1, A2, WQ1, WQ2, WK1, WK2, WV1, WV2,
        mxA, mxQ, mxK, mxV, qraw, kraw, vraw);

    // ---- fused norm / rope / pack ----
    normpack_all<<<6144, 256>>>(qraw, kraw, vraw, qw, kw, cosb, sinb,
                                QH, QL, KHp, KLp, VHp, VLp);

    // ---- flash (R12 proven) with fused ctx row-max ----
    flash_bf16<<<dim3(NH_, B_, 16), 128, FLASH_SMEM>>>(
        QH, QL, KHp, KLp, VHp, VLp, ctx, mxC);

    // ---- output projection (rowmax already done by flash) ----
    tquant<<<dim3(64, 32), 256>>>(ctx, mxC, A1, A2, 2048, 2048);
    gemm_i8<<<dim3(16, 16), 256, G2_SMEM>>>(A1, A2, WO1, WO2, mxC, mxO,
                                            out, 2048, 2048, 2048);
}